// round 1
// baseline (speedup 1.0000x reference)
#include <cuda_runtime.h>
#include <math.h>
#include <stdint.h>

// Problem constants
#define BB   2
#define SS   2048
#define HH   2048
#define NH   16
#define DD   128
#define NROWS (BB*SS)          // 4096
#define KDIM  HH               // 2048
#define SCALE 0.08838834764831845f  // 1/sqrt(128)

// ---------------- scratch (device globals; no allocation allowed) -------------
__device__ float g_h[NROWS*HH];
__device__ float g_q[NROWS*HH];
__device__ float g_k[NROWS*HH];
__device__ float g_v[NROWS*HH];
__device__ float g_ctx[NROWS*HH];
__device__ float g_cos[SS*64];
__device__ float g_sin[SS*64];

// ---------------- RoPE tables (double precision, tiny) ------------------------
__global__ void rope_table_kernel() {
    int idx = blockIdx.x * blockDim.x + threadIdx.x;
    if (idx >= SS * 64) return;
    int s = idx >> 6;
    int j = idx & 63;
    double inv = exp(-log(10000.0) * (double)(2 * j) / 128.0);
    double a = (double)s * inv;
    g_cos[idx] = (float)cos(a);
    g_sin[idx] = (float)sin(a);
}

// ---------------- RMSNorm: one block per row ----------------------------------
__global__ void __launch_bounds__(256) rmsnorm_kernel(const float* __restrict__ x,
                                                      const float* __restrict__ w) {
    int row = blockIdx.x;
    const float* xr = x + (size_t)row * HH;
    float* hr = g_h + (size_t)row * HH;
    int tid = threadIdx.x;

    float ss = 0.f;
#pragma unroll
    for (int t = 0; t < 8; t++) {
        float v = xr[tid + t * 256];
        ss += v * v;
    }
    // warp reduce
#pragma unroll
    for (int off = 16; off >= 1; off >>= 1)
        ss += __shfl_xor_sync(0xffffffffu, ss, off);
    __shared__ float red[8];
    if ((tid & 31) == 0) red[tid >> 5] = ss;
    __syncthreads();
    float tot = red[0] + red[1] + red[2] + red[3] + red[4] + red[5] + red[6] + red[7];
    float invn = rsqrtf(tot * (1.0f / (float)HH) + 1e-6f);
#pragma unroll
    for (int t = 0; t < 8; t++) {
        int c = tid + t * 256;
        hr[c] = w[c] * (xr[c] * invn);
    }
}

// ---------------- GEMM: C[M,N] = A[M,K] * B[N,K]^T  (all K-major) -------------
// BM=BN=128, BK=16, 256 threads, 8x8 per thread. blockIdx.z selects (B,C) pair.
__global__ void __launch_bounds__(256, 2)
gemm_kernel(const float* __restrict__ A,
            const float* __restrict__ B0, const float* __restrict__ B1,
            const float* __restrict__ B2,
            float* __restrict__ C0, float* __restrict__ C1, float* __restrict__ C2) {
    const float* Bw = (blockIdx.z == 0) ? B0 : ((blockIdx.z == 1) ? B1 : B2);
    float* C = (blockIdx.z == 0) ? C0 : ((blockIdx.z == 1) ? C1 : C2);

    __shared__ float As[16][132];   // As[k][m]
    __shared__ float Bs[16][132];   // Bs[k][n]

    int tid = threadIdx.x;
    int bm = blockIdx.y * 128;
    int bn = blockIdx.x * 128;
    int ty = tid >> 4, tx = tid & 15;

    int lr = tid >> 2;            // 0..63
    int lc = (tid & 3) << 2;      // 0,4,8,12

    float acc[8][8];
#pragma unroll
    for (int i = 0; i < 8; i++)
#pragma unroll
        for (int j = 0; j < 8; j++) acc[i][j] = 0.f;

    const float* Arow0 = A + (size_t)(bm + lr) * KDIM + lc;
    const float* Arow1 = A + (size_t)(bm + lr + 64) * KDIM + lc;
    const float* Brow0 = Bw + (size_t)(bn + lr) * KDIM + lc;
    const float* Brow1 = Bw + (size_t)(bn + lr + 64) * KDIM + lc;

    for (int kt = 0; kt < KDIM; kt += 16) {
        float4 a0 = *(const float4*)(Arow0 + kt);
        float4 a1 = *(const float4*)(Arow1 + kt);
        float4 b0 = *(const float4*)(Brow0 + kt);
        float4 b1 = *(const float4*)(Brow1 + kt);
        __syncthreads();
        As[lc + 0][lr] = a0.x; As[lc + 1][lr] = a0.y; As[lc + 2][lr] = a0.z; As[lc + 3][lr] = a0.w;
        As[lc + 0][lr + 64] = a1.x; As[lc + 1][lr + 64] = a1.y; As[lc + 2][lr + 64] = a1.z; As[lc + 3][lr + 64] = a1.w;
        Bs[lc + 0][lr] = b0.x; Bs[lc + 1][lr] = b0.y; Bs[lc + 2][lr] = b0.z; Bs[lc + 3][lr] = b0.w;
        Bs[lc + 0][lr + 64] = b1.x; Bs[lc + 1][lr + 64] = b1.y; Bs[lc + 2][lr + 64] = b1.z; Bs[lc + 3][lr + 64] = b1.w;
        __syncthreads();
#pragma unroll
        for (int k = 0; k < 16; k++) {
            float4 af0 = *(const float4*)&As[k][ty * 8];
            float4 af1 = *(const float4*)&As[k][ty * 8 + 4];
            float4 bf0 = *(const float4*)&Bs[k][tx * 8];
            float4 bf1 = *(const float4*)&Bs[k][tx * 8 + 4];
            float a[8] = {af0.x, af0.y, af0.z, af0.w, af1.x, af1.y, af1.z, af1.w};
            float b[8] = {bf0.x, bf0.y, bf0.z, bf0.w, bf1.x, bf1.y, bf1.z, bf1.w};
#pragma unroll
            for (int i = 0; i < 8; i++)
#pragma unroll
                for (int j = 0; j < 8; j++) acc[i][j] = fmaf(a[i], b[j], acc[i][j]);
        }
    }
#pragma unroll
    for (int i = 0; i < 8; i++) {
        float* crow = C + (size_t)(bm + ty * 8 + i) * HH + bn + tx * 8;
        *(float4*)(crow) = make_float4(acc[i][0], acc[i][1], acc[i][2], acc[i][3]);
        *(float4*)(crow + 4) = make_float4(acc[i][4], acc[i][5], acc[i][6], acc[i][7]);
    }
}

// ---------------- RoPE apply (in place on g_q, g_k) ---------------------------
__global__ void rope_apply_kernel(const int* __restrict__ pos_ids) {
    int idx = blockIdx.x * blockDim.x + threadIdx.x;  // NROWS*NH*64
    if (idx >= NROWS * NH * 64) return;
    int j = idx & 63;
    int head = (idx >> 6) & 15;
    int n = idx >> 10;                 // 0..4095 = b*S+s
    int pos = pos_ids[n];
    float c = g_cos[pos * 64 + j];
    float s = g_sin[pos * 64 + j];
    size_t off = (size_t)n * HH + head * DD;
    float q1 = g_q[off + j], q2 = g_q[off + j + 64];
    g_q[off + j] = q1 * c - q2 * s;
    g_q[off + j + 64] = q2 * c + q1 * s;
    float k1 = g_k[off + j], k2 = g_k[off + j + 64];
    g_k[off + j] = k1 * c - k2 * s;
    g_k[off + j + 64] = k2 * c + k1 * s;
}

// ---------------- flash attention (fp32, causal) ------------------------------
// block = (q_tile of 64, b*NH). 256 threads. Online softmax. Masked-out key
// tiles (kt > qt) skipped: exp(s - 10000 - m) == 0 in fp32, same as reference.
#define AD 68   // padded 64

__global__ void __launch_bounds__(256) flash_kernel() {
    extern __shared__ float sm[];
    float* Qs = sm;                    // [128][AD]  Qs[d][m]
    float* Ks = Qs + 128 * AD;         // [128][AD]  Ks[d][n]
    float* Vs = Ks + 128 * AD;         // [64][128]  Vs[n][d]
    float* Ps = Vs + 64 * 128;         // [64][AD]   Ps[n][m]

    int bh = blockIdx.y;               // b*NH + h
    int b = bh >> 4, h = bh & 15;
    int qt = blockIdx.x;
    int tid = threadIdx.x;
    int ty = tid >> 4, tx = tid & 15;

    const float* Qbase = g_q + ((size_t)(b * SS + qt * 64)) * HH + h * DD;

    // load Q tile transposed
#pragma unroll
    for (int t = 0; t < 8; t++) {
        int sIdx = tid + t * 256;       // 0..2047 float4 slots
        int r = sIdx >> 5;
        int c4 = (sIdx & 31) << 2;
        float4 v = *(const float4*)&Qbase[(size_t)r * HH + c4];
        Qs[(c4 + 0) * AD + r] = v.x;
        Qs[(c4 + 1) * AD + r] = v.y;
        Qs[(c4 + 2) * AD + r] = v.z;
        Qs[(c4 + 3) * AD + r] = v.w;
    }

    float m_cur[4], l_cur[4], oacc[4][8];
#pragma unroll
    for (int i = 0; i < 4; i++) {
        m_cur[i] = -1e30f;
        l_cur[i] = 0.f;
#pragma unroll
        for (int j = 0; j < 8; j++) oacc[i][j] = 0.f;
    }

    for (int kt = 0; kt <= qt; kt++) {
        const float* Kbase = g_k + ((size_t)(b * SS + kt * 64)) * HH + h * DD;
        const float* Vbase = g_v + ((size_t)(b * SS + kt * 64)) * HH + h * DD;
        __syncthreads();   // prev-iter compute done; Q stores visible (iter 0)
#pragma unroll
        for (int t = 0; t < 8; t++) {
            int sIdx = tid + t * 256;
            int r = sIdx >> 5;
            int c4 = (sIdx & 31) << 2;
            float4 v = *(const float4*)&Kbase[(size_t)r * HH + c4];
            Ks[(c4 + 0) * AD + r] = v.x;
            Ks[(c4 + 1) * AD + r] = v.y;
            Ks[(c4 + 2) * AD + r] = v.z;
            Ks[(c4 + 3) * AD + r] = v.w;
            float4 vv = *(const float4*)&Vbase[(size_t)r * HH + c4];
            *(float4*)&Vs[r * 128 + c4] = vv;
        }
        __syncthreads();

        // scores 64x64: thread owns rows ty*4+i, cols tx*4+j
        float sacc[4][4];
#pragma unroll
        for (int i = 0; i < 4; i++)
#pragma unroll
            for (int j = 0; j < 4; j++) sacc[i][j] = 0.f;
#pragma unroll 16
        for (int d = 0; d < 128; d++) {
            float4 q4 = *(const float4*)&Qs[d * AD + ty * 4];
            float4 k4 = *(const float4*)&Ks[d * AD + tx * 4];
            float qa[4] = {q4.x, q4.y, q4.z, q4.w};
            float ka[4] = {k4.x, k4.y, k4.z, k4.w};
#pragma unroll
            for (int i = 0; i < 4; i++)
#pragma unroll
                for (int j = 0; j < 4; j++) sacc[i][j] = fmaf(qa[i], ka[j], sacc[i][j]);
        }
        // scale + causal mask (diag tile only)
        if (kt == qt) {
#pragma unroll
            for (int i = 0; i < 4; i++)
#pragma unroll
                for (int j = 0; j < 4; j++) {
                    float v = sacc[i][j] * SCALE;
                    if (tx * 4 + j > ty * 4 + i) v -= 10000.f;
                    sacc[i][j] = v;
                }
        } else {
#pragma unroll
            for (int i = 0; i < 4; i++)
#pragma unroll
                for (int j = 0; j < 4; j++) sacc[i][j] *= SCALE;
        }
        // row max across 16-lane group
        float rmax[4];
#pragma unroll
        for (int i = 0; i < 4; i++) {
            float m = fmaxf(fmaxf(sacc[i][0], sacc[i][1]), fmaxf(sacc[i][2], sacc[i][3]));
#pragma unroll
            for (int off = 8; off >= 1; off >>= 1)
                m = fmaxf(m, __shfl_xor_sync(0xffffffffu, m, off));
            rmax[i] = m;
        }
        float mnew[4], alpha[4];
#pragma unroll
        for (int i = 0; i < 4; i++) {
            mnew[i] = fmaxf(m_cur[i], rmax[i]);
            alpha[i] = __expf(m_cur[i] - mnew[i]);
            m_cur[i] = mnew[i];
        }
        float p[4][4], rsum[4];
#pragma unroll
        for (int i = 0; i < 4; i++) {
            rsum[i] = 0.f;
#pragma unroll
            for (int j = 0; j < 4; j++) {
                p[i][j] = __expf(sacc[i][j] - mnew[i]);
                rsum[i] += p[i][j];
            }
#pragma unroll
            for (int off = 8; off >= 1; off >>= 1)
                rsum[i] += __shfl_xor_sync(0xffffffffu, rsum[i], off);
            l_cur[i] = l_cur[i] * alpha[i] + rsum[i];
#pragma unroll
            for (int j = 0; j < 8; j++) oacc[i][j] *= alpha[i];
        }
        // store P transposed: Ps[n][m]
#pragma unroll
        for (int j = 0; j < 4; j++)
            *(float4*)&Ps[(tx * 4 + j) * AD + ty * 4] =
                make_float4(p[0][j], p[1][j], p[2][j], p[3][j]);
        __syncthreads();

        // O += P * V
#pragma unroll 8
        for (int k = 0; k < 64; k++) {
            float4 pv = *(const float4*)&Ps[k * AD + ty * 4];
            float4 v0 = *(const float4*)&Vs[k * 128 + tx * 8];
            float4 v1 = *(const float4*)&Vs[k * 128 + tx * 8 + 4];
            float pa[4] = {pv.x, pv.y, pv.z, pv.w};
            float va[8] = {v0.x, v0.y, v0.z, v0.w, v1.x, v1.y, v1.z, v1.w};
#pragma unroll
            for (int i = 0; i < 4; i++)
#pragma unroll
                for (int j = 0; j < 8; j++) oacc[i][j] = fmaf(pa[i], va[j], oacc[i][j]);
        }
    }

    // normalize and write ctx
    float* Ob = g_ctx + ((size_t)(b * SS + qt * 64)) * HH + h * DD;
#pragma unroll
    for (int i = 0; i < 4; i++) {
        float inv = 1.f / l_cur[i];
        float* row = Ob + (size_t)(ty * 4 + i) * HH + tx * 8;
        *(float4*)(row) = make_float4(oacc[i][0] * inv, oacc[i][1] * inv,
                                      oacc[i][2] * inv, oacc[i][3] * inv);
        *(float4*)(row + 4) = make_float4(oacc[i][4] * inv, oacc[i][5] * inv,
                                          oacc[i][6] * inv, oacc[i][7] * inv);
    }
}

// ---------------- launch -------------------------------------------------------
extern "C" void kernel_launch(void* const* d_in, const int* in_sizes, int n_in,
                              void* d_out, int out_size) {
    const float* x      = (const float*)d_in[0];
    const float* norm_w = (const float*)d_in[1];
    const float* wq     = (const float*)d_in[2];
    const float* wk     = (const float*)d_in[3];
    const float* wv     = (const float*)d_in[4];
    const float* wo     = (const float*)d_in[5];
    const int*   pos    = (const int*)d_in[6];
    float* out = (float*)d_out;

    float *ph, *pq, *pk, *pv, *pctx;
    cudaGetSymbolAddress((void**)&ph, g_h);
    cudaGetSymbolAddress((void**)&pq, g_q);
    cudaGetSymbolAddress((void**)&pk, g_k);
    cudaGetSymbolAddress((void**)&pv, g_v);
    cudaGetSymbolAddress((void**)&pctx, g_ctx);

    // RoPE tables
    rope_table_kernel<<<(SS * 64 + 255) / 256, 256>>>();
    // RMSNorm
    rmsnorm_kernel<<<NROWS, 256>>>(x, norm_w);
    // QKV projections
    gemm_kernel<<<dim3(HH / 128, NROWS / 128, 3), 256>>>(ph, wq, wk, wv, pq, pk, pv);
    // RoPE
    rope_apply_kernel<<<(NROWS * NH * 64 + 255) / 256, 256>>>(pos);
    // attention
    int smem = (128 * AD + 128 * AD + 64 * 128 + 64 * AD) * (int)sizeof(float);
    cudaFuncSetAttribute(flash_kernel, cudaFuncAttributeMaxDynamicSharedMemorySize, smem);
    flash_kernel<<<dim3(SS / 64, BB * NH), 256, smem>>>();
    // output projection
    gemm_kernel<<<dim3(HH / 128, NROWS / 128, 1), 256>>>(pctx, wo, wo, wo, out, out, out);
}

// round 5
// speedup vs baseline: 1.5579x; 1.5579x over previous
#include <cuda_runtime.h>
#include <cuda_bf16.h>
#include <math.h>
#include <stdint.h>

// Problem constants
#define BB   2
#define SS   2048
#define HH   2048
#define NH   16
#define DD   128
#define NROWS (BB*SS)          // 4096
#define KDIM  HH               // 2048
#define SCALE 0.08838834764831845f  // 1/sqrt(128)

__device__ __forceinline__ uint32_t smem_u32(const void* p) {
    uint32_t a;
    asm("{ .reg .u64 t; cvta.to.shared.u64 t, %1; cvt.u32.u64 %0, t; }" : "=r"(a) : "l"(p));
    return a;
}

#define LDSM4(R0, R1, R2, R3, ADDR) \
    asm volatile("ldmatrix.sync.aligned.m8n8.x4.shared.b16 {%0,%1,%2,%3}, [%4];" \
        : "=r"(R0), "=r"(R1), "=r"(R2), "=r"(R3) : "r"(ADDR))

#define MMA16816(D, A, B0, B1) \
    asm volatile("mma.sync.aligned.m16n8k16.row.col.f32.bf16.bf16.f32 " \
        "{%0,%1,%2,%3}, {%4,%5,%6,%7}, {%8,%9}, {%0,%1,%2,%3};" \
        : "+f"((D)[0]), "+f"((D)[1]), "+f"((D)[2]), "+f"((D)[3]) \
        : "r"((A)[0]), "r"((A)[1]), "r"((A)[2]), "r"((A)[3]), "r"(B0), "r"(B1))

#define CP_ASYNC16(DST, SRC) \
    asm volatile("cp.async.cg.shared.global [%0], [%1], 16;" :: "r"(DST), "l"(SRC))
#define CP_COMMIT() asm volatile("cp.async.commit_group;" ::: "memory")
#define CP_WAIT1()  asm volatile("cp.async.wait_group 1;" ::: "memory")
#define CP_WAIT0()  asm volatile("cp.async.wait_group 0;" ::: "memory")

// ============================ scratch globals =================================
__device__ __nv_bfloat16 g_h_hi[NROWS * HH];
__device__ __nv_bfloat16 g_h_lo[NROWS * HH];
__device__ __nv_bfloat16 g_w_hi[4 * HH * HH];
__device__ __nv_bfloat16 g_w_lo[4 * HH * HH];
__device__ __nv_bfloat16 g_ctx_hi[NROWS * HH];
__device__ __nv_bfloat16 g_ctx_lo[NROWS * HH];
__device__ float g_q[NROWS * HH];
__device__ float g_k[NROWS * HH];
__device__ float g_v[NROWS * HH];
__device__ float g_cos[SS * 64];
__device__ float g_sin[SS * 64];

// ============================ RoPE tables =====================================
__global__ void rope_table_kernel() {
    int idx = blockIdx.x * blockDim.x + threadIdx.x;
    if (idx >= SS * 64) return;
    int s = idx >> 6;
    int j = idx & 63;
    double inv = exp(-log(10000.0) * (double)(2 * j) / 128.0);
    double a = (double)s * inv;
    g_cos[idx] = (float)cos(a);
    g_sin[idx] = (float)sin(a);
}

// ============================ weight split ====================================
__global__ void __launch_bounds__(256) convert_w_kernel(const float* __restrict__ wq,
                                                        const float* __restrict__ wk,
                                                        const float* __restrict__ wv,
                                                        const float* __restrict__ wo) {
    int z = blockIdx.y;
    const float* src = (z == 0) ? wq : (z == 1) ? wk : (z == 2) ? wv : wo;
    size_t i = (size_t)blockIdx.x * 1024 + threadIdx.x * 4;
    if (i >= (size_t)HH * HH) return;
    float4 v = *(const float4*)(src + i);
    size_t o = (size_t)z * HH * HH + i;
    float vv[4] = {v.x, v.y, v.z, v.w};
#pragma unroll
    for (int t = 0; t < 4; t++) {
        __nv_bfloat16 hi = __float2bfloat16(vv[t]);
        g_w_hi[o + t] = hi;
        g_w_lo[o + t] = __float2bfloat16(vv[t] - __bfloat162float(hi));
    }
}

// ============================ RMSNorm → bf16 hi/lo ============================
__global__ void __launch_bounds__(256) rmsnorm_kernel(const float* __restrict__ x,
                                                      const float* __restrict__ w) {
    int row = blockIdx.x;
    const float* xr = x + (size_t)row * HH;
    int tid = threadIdx.x;

    float ss = 0.f;
#pragma unroll
    for (int t = 0; t < 8; t++) {
        float v = xr[tid + t * 256];
        ss += v * v;
    }
#pragma unroll
    for (int off = 16; off >= 1; off >>= 1)
        ss += __shfl_xor_sync(0xffffffffu, ss, off);
    __shared__ float red[8];
    if ((tid & 31) == 0) red[tid >> 5] = ss;
    __syncthreads();
    float tot = red[0] + red[1] + red[2] + red[3] + red[4] + red[5] + red[6] + red[7];
    float invn = rsqrtf(tot * (1.0f / (float)HH) + 1e-6f);
    size_t base = (size_t)row * HH;
#pragma unroll
    for (int t = 0; t < 8; t++) {
        int c = tid + t * 256;
        float v = w[c] * (xr[c] * invn);
        __nv_bfloat16 hi = __float2bfloat16(v);
        g_h_hi[base + c] = hi;
        g_h_lo[base + c] = __float2bfloat16(v - __bfloat162float(hi));
    }
}

// ============ HMMA GEMM: C[M,N] = A[M,K] * W[N,K]^T (3-term bf16 split) =======
// CTA 128x128, BK=32, 256 threads = 8 warps (2 M x 4 N), warp tile 64x32.
// SMEM rows padded to 40 bf16 (80 B): ldmatrix stride 5 units mod 8 -> conflict-free.
#define GBM 128
#define GBN 128
#define GBK 32
#define LDA_B 80                      // bytes per padded smem row (40 bf16)
#define ARR_BYTES (128 * LDA_B)       // 10240
#define S_AH 0
#define S_AL (1 * ARR_BYTES)
#define S_BH (2 * ARR_BYTES)
#define S_BL (3 * ARR_BYTES)
#define STAGE (4 * ARR_BYTES)         // 40960
#define GEMM_SMEM (2 * STAGE)         // 81920
#define NC (KDIM / GBK)               // 64

__global__ void __launch_bounds__(256, 1)
hmma_gemm(const __nv_bfloat16* __restrict__ Ahp, const __nv_bfloat16* __restrict__ Alp,
          const __nv_bfloat16* __restrict__ Whp, const __nv_bfloat16* __restrict__ Wlp,
          float* __restrict__ C0, float* __restrict__ C1, float* __restrict__ C2) {
    extern __shared__ char smem[];
    uint32_t sb = smem_u32(smem);
    int tid = threadIdx.x;
    int wid = tid >> 5, lane = tid & 31;
    int bm = blockIdx.y * GBM;
    int bn = blockIdx.x * GBN;
    int z = blockIdx.z;
    const __nv_bfloat16* wh = Whp + (size_t)z * HH * HH;
    const __nv_bfloat16* wl = Wlp + (size_t)z * HH * HH;
    float* C = (z == 0) ? C0 : ((z == 1) ? C1 : C2);

    // GMEM bases (16B units; K row = 2048 bf16 = 256 uint4)
    const uint4* gAh = (const uint4*)Ahp + (size_t)bm * 256;
    const uint4* gAl = (const uint4*)Alp + (size_t)bm * 256;
    const uint4* gBh = (const uint4*)wh + (size_t)bn * 256;
    const uint4* gBl = (const uint4*)wl + (size_t)bn * 256;

    // load mapping: 512 uint4 per array, 2 per thread (u = tid + 256*i)
    int r0 = tid >> 2, c0 = tid & 3;            // u = tid
    int r1 = (tid + 256) >> 2, c1 = tid & 3;    // u = tid+256

#define ISSUE(chunk, buf) do { \
    uint32_t st_ = sb + (buf) * STAGE; \
    size_t g0_ = (size_t)r0 * 256 + (chunk) * 4 + c0; \
    size_t g1_ = (size_t)r1 * 256 + (chunk) * 4 + c1; \
    uint32_t s0_ = r0 * LDA_B + c0 * 16; \
    uint32_t s1_ = r1 * LDA_B + c1 * 16; \
    CP_ASYNC16(st_ + S_AH + s0_, gAh + g0_); \
    CP_ASYNC16(st_ + S_AH + s1_, gAh + g1_); \
    CP_ASYNC16(st_ + S_AL + s0_, gAl + g0_); \
    CP_ASYNC16(st_ + S_AL + s1_, gAl + g1_); \
    CP_ASYNC16(st_ + S_BH + s0_, gBh + g0_); \
    CP_ASYNC16(st_ + S_BH + s1_, gBh + g1_); \
    CP_ASYNC16(st_ + S_BL + s0_, gBl + g0_); \
    CP_ASYNC16(st_ + S_BL + s1_, gBl + g1_); \
} while (0)

    int wm = wid >> 2;   // 0..1 : M offset wm*64
    int wn = wid & 3;    // 0..3 : N offset wn*32

    // ldmatrix base offsets (bytes, within array)
    uint32_t a_base = (uint32_t)(wm * 64 + (lane & 15)) * LDA_B + (lane >> 4) * 16;
    int q = lane >> 3;
    uint32_t b_base = (uint32_t)(wn * 32 + ((q >> 1) * 8) + (lane & 7)) * LDA_B + (q & 1) * 16;

    float acc[4][4][4];
#pragma unroll
    for (int mi = 0; mi < 4; mi++)
#pragma unroll
        for (int ni = 0; ni < 4; ni++)
#pragma unroll
            for (int e = 0; e < 4; e++) acc[mi][ni][e] = 0.f;

    ISSUE(0, 0);
    CP_COMMIT();

    for (int c = 0; c < NC; c++) {
        int buf = c & 1;
        if (c + 1 < NC) {
            ISSUE(c + 1, (c + 1) & 1);
            CP_COMMIT();
            CP_WAIT1();
        } else {
            CP_WAIT0();
        }
        __syncthreads();

        uint32_t st = sb + buf * STAGE;
#pragma unroll
        for (int ks = 0; ks < 2; ks++) {
            uint32_t a_hi[4][4], a_lo[4][4], b_hi[2][4], b_lo[2][4];
#pragma unroll
            for (int mi = 0; mi < 4; mi++) {
                uint32_t ao = a_base + mi * (16 * LDA_B) + ks * 32;
                LDSM4(a_hi[mi][0], a_hi[mi][1], a_hi[mi][2], a_hi[mi][3], st + S_AH + ao);
                LDSM4(a_lo[mi][0], a_lo[mi][1], a_lo[mi][2], a_lo[mi][3], st + S_AL + ao);
            }
#pragma unroll
            for (int nj = 0; nj < 2; nj++) {
                uint32_t bo = b_base + nj * (16 * LDA_B) + ks * 32;
                LDSM4(b_hi[nj][0], b_hi[nj][1], b_hi[nj][2], b_hi[nj][3], st + S_BH + bo);
                LDSM4(b_lo[nj][0], b_lo[nj][1], b_lo[nj][2], b_lo[nj][3], st + S_BL + bo);
            }
#pragma unroll
            for (int mi = 0; mi < 4; mi++)
#pragma unroll
                for (int ni = 0; ni < 4; ni++) {
                    int nj = ni >> 1, sel = (ni & 1) * 2;
                    MMA16816(acc[mi][ni], a_hi[mi], b_hi[nj][sel], b_hi[nj][sel + 1]);
                    MMA16816(acc[mi][ni], a_hi[mi], b_lo[nj][sel], b_lo[nj][sel + 1]);
                    MMA16816(acc[mi][ni], a_lo[mi], b_hi[nj][sel], b_hi[nj][sel + 1]);
                }
        }
        __syncthreads();
    }

    // epilogue
    int row_in = (lane >> 2);
    int col_in = (lane & 3) * 2;
#pragma unroll
    for (int mi = 0; mi < 4; mi++) {
        int grow = bm + wm * 64 + mi * 16 + row_in;
#pragma unroll
        for (int ni = 0; ni < 4; ni++) {
            int gcol = bn + wn * 32 + ni * 8 + col_in;
            float* cr = C + (size_t)grow * HH + gcol;
            cr[0] = acc[mi][ni][0];
            cr[1] = acc[mi][ni][1];
            float* cr2 = cr + 8 * HH;
            cr2[0] = acc[mi][ni][2];
            cr2[1] = acc[mi][ni][3];
        }
    }
}

// ============================ RoPE apply ======================================
__global__ void rope_apply_kernel(const int* __restrict__ pos_ids) {
    int idx = blockIdx.x * blockDim.x + threadIdx.x;
    if (idx >= NROWS * NH * 64) return;
    int j = idx & 63;
    int head = (idx >> 6) & 15;
    int n = idx >> 10;
    int pos = pos_ids[n];
    float c = g_cos[pos * 64 + j];
    float s = g_sin[pos * 64 + j];
    size_t off = (size_t)n * HH + head * DD;
    float q1 = g_q[off + j], q2 = g_q[off + j + 64];
    g_q[off + j] = q1 * c - q2 * s;
    g_q[off + j + 64] = q2 * c + q1 * s;
    float k1 = g_k[off + j], k2 = g_k[off + j + 64];
    g_k[off + j] = k1 * c - k2 * s;
    g_k[off + j + 64] = k2 * c + k1 * s;
}

// ============================ flash attention (fp32) ==========================
#define AD 68

__global__ void __launch_bounds__(256) flash_kernel() {
    extern __shared__ float sm[];
    float* Qs = sm;                    // [128][AD]
    float* Ks = Qs + 128 * AD;         // [128][AD]
    float* Vs = Ks + 128 * AD;         // [64][128]
    float* Ps = Vs + 64 * 128;         // [64][AD]

    int bh = blockIdx.y;
    int b = bh >> 4, h = bh & 15;
    int qt = blockIdx.x;
    int tid = threadIdx.x;
    int ty = tid >> 4, tx = tid & 15;

    const float* Qbase = g_q + ((size_t)(b * SS + qt * 64)) * HH + h * DD;

#pragma unroll
    for (int t = 0; t < 8; t++) {
        int sIdx = tid + t * 256;
        int r = sIdx >> 5;
        int c4 = (sIdx & 31) << 2;
        float4 v = *(const float4*)&Qbase[(size_t)r * HH + c4];
        Qs[(c4 + 0) * AD + r] = v.x;
        Qs[(c4 + 1) * AD + r] = v.y;
        Qs[(c4 + 2) * AD + r] = v.z;
        Qs[(c4 + 3) * AD + r] = v.w;
    }

    float m_cur[4], l_cur[4], oacc[4][8];
#pragma unroll
    for (int i = 0; i < 4; i++) {
        m_cur[i] = -1e30f;
        l_cur[i] = 0.f;
#pragma unroll
        for (int j = 0; j < 8; j++) oacc[i][j] = 0.f;
    }

    for (int kt = 0; kt <= qt; kt++) {
        const float* Kbase = g_k + ((size_t)(b * SS + kt * 64)) * HH + h * DD;
        const float* Vbase = g_v + ((size_t)(b * SS + kt * 64)) * HH + h * DD;
        __syncthreads();
#pragma unroll
        for (int t = 0; t < 8; t++) {
            int sIdx = tid + t * 256;
            int r = sIdx >> 5;
            int c4 = (sIdx & 31) << 2;
            float4 v = *(const float4*)&Kbase[(size_t)r * HH + c4];
            Ks[(c4 + 0) * AD + r] = v.x;
            Ks[(c4 + 1) * AD + r] = v.y;
            Ks[(c4 + 2) * AD + r] = v.z;
            Ks[(c4 + 3) * AD + r] = v.w;
            float4 vv = *(const float4*)&Vbase[(size_t)r * HH + c4];
            *(float4*)&Vs[r * 128 + c4] = vv;
        }
        __syncthreads();

        float sacc[4][4];
#pragma unroll
        for (int i = 0; i < 4; i++)
#pragma unroll
            for (int j = 0; j < 4; j++) sacc[i][j] = 0.f;
#pragma unroll 16
        for (int d = 0; d < 128; d++) {
            float4 q4 = *(const float4*)&Qs[d * AD + ty * 4];
            float4 k4 = *(const float4*)&Ks[d * AD + tx * 4];
            float qa[4] = {q4.x, q4.y, q4.z, q4.w};
            float ka[4] = {k4.x, k4.y, k4.z, k4.w};
#pragma unroll
            for (int i = 0; i < 4; i++)
#pragma unroll
                for (int j = 0; j < 4; j++) sacc[i][j] = fmaf(qa[i], ka[j], sacc[i][j]);
        }
        if (kt == qt) {
#pragma unroll
            for (int i = 0; i < 4; i++)
#pragma unroll
                for (int j = 0; j < 4; j++) {
                    float v = sacc[i][j] * SCALE;
                    if (tx * 4 + j > ty * 4 + i) v -= 10000.f;
                    sacc[i][j] = v;
                }
        } else {
#pragma unroll
            for (int i = 0; i < 4; i++)
#pragma unroll
                for (int j = 0; j < 4; j++) sacc[i][j] *= SCALE;
        }
        float rmax[4];
#pragma unroll
        for (int i = 0; i < 4; i++) {
            float m = fmaxf(fmaxf(sacc[i][0], sacc[i][1]), fmaxf(sacc[i][2], sacc[i][3]));
#pragma unroll
            for (int off = 8; off >= 1; off >>= 1)
                m = fmaxf(m, __shfl_xor_sync(0xffffffffu, m, off));
            rmax[i] = m;
        }
        float mnew[4], alpha[4];
#pragma unroll
        for (int i = 0; i < 4; i++) {
            mnew[i] = fmaxf(m_cur[i], rmax[i]);
            alpha[i] = __expf(m_cur[i] - mnew[i]);
            m_cur[i] = mnew[i];
        }
        float p[4][4], rsum[4];
#pragma unroll
        for (int i = 0; i < 4; i++) {
            rsum[i] = 0.f;
#pragma unroll
            for (int j = 0; j < 4; j++) {
                p[i][j] = __expf(sacc[i][j] - mnew[i]);
                rsum[i] += p[i][j];
            }
#pragma unroll
            for (int off = 8; off >= 1; off >>= 1)
                rsum[i] += __shfl_xor_sync(0xffffffffu, rsum[i], off);
            l_cur[i] = l_cur[i] * alpha[i] + rsum[i];
#pragma unroll
            for (int j = 0; j < 8; j++) oacc[i][j] *= alpha[i];
        }
#pragma unroll
        for (int j = 0; j < 4; j++)
            *(float4*)&Ps[(tx * 4 + j) * AD + ty * 4] =
                make_float4(p[0][j], p[1][j], p[2][j], p[3][j]);
        __syncthreads();

#pragma unroll 8
        for (int k = 0; k < 64; k++) {
            float4 pv = *(const float4*)&Ps[k * AD + ty * 4];
            float4 v0 = *(const float4*)&Vs[k * 128 + tx * 8];
            float4 v1 = *(const float4*)&Vs[k * 128 + tx * 8 + 4];
            float pa[4] = {pv.x, pv.y, pv.z, pv.w};
            float va[8] = {v0.x, v0.y, v0.z, v0.w, v1.x, v1.y, v1.z, v1.w};
#pragma unroll
            for (int i = 0; i < 4; i++)
#pragma unroll
                for (int j = 0; j < 8; j++) oacc[i][j] = fmaf(pa[i], va[j], oacc[i][j]);
        }
    }

    // epilogue: write ctx as bf16 hi/lo for the wo GEMM
    size_t base = ((size_t)(b * SS + qt * 64)) * HH + h * DD;
#pragma unroll
    for (int i = 0; i < 4; i++) {
        float inv = 1.f / l_cur[i];
        size_t ro = base + (size_t)(ty * 4 + i) * HH + tx * 8;
#pragma unroll
        for (int j = 0; j < 8; j++) {
            float o = oacc[i][j] * inv;
            __nv_bfloat16 hi = __float2bfloat16(o);
            g_ctx_hi[ro + j] = hi;
            g_ctx_lo[ro + j] = __float2bfloat16(o - __bfloat162float(hi));
        }
    }
}

// ============================ launch ==========================================
extern "C" void kernel_launch(void* const* d_in, const int* in_sizes, int n_in,
                              void* d_out, int out_size) {
    const float* x      = (const float*)d_in[0];
    const float* norm_w = (const float*)d_in[1];
    const float* wq     = (const float*)d_in[2];
    const float* wk     = (const float*)d_in[3];
    const float* wv     = (const float*)d_in[4];
    const float* wo     = (const float*)d_in[5];
    const int*   pos    = (const int*)d_in[6];
    float* out = (float*)d_out;

    __nv_bfloat16 *phh, *phl, *pwh, *pwl, *pch, *pcl;
    float *pq, *pk, *pv;
    cudaGetSymbolAddress((void**)&phh, g_h_hi);
    cudaGetSymbolAddress((void**)&phl, g_h_lo);
    cudaGetSymbolAddress((void**)&pwh, g_w_hi);
    cudaGetSymbolAddress((void**)&pwl, g_w_lo);
    cudaGetSymbolAddress((void**)&pch, g_ctx_hi);
    cudaGetSymbolAddress((void**)&pcl, g_ctx_lo);
    cudaGetSymbolAddress((void**)&pq, g_q);
    cudaGetSymbolAddress((void**)&pk, g_k);
    cudaGetSymbolAddress((void**)&pv, g_v);

    int fs = (128 * AD + 128 * AD + 64 * 128 + 64 * AD) * (int)sizeof(float);
    cudaFuncSetAttribute(hmma_gemm, cudaFuncAttributeMaxDynamicSharedMemorySize, GEMM_SMEM);
    cudaFuncSetAttribute(flash_kernel, cudaFuncAttributeMaxDynamicSharedMemorySize, fs);

    rope_table_kernel<<<(SS * 64 + 255) / 256, 256>>>();
    convert_w_kernel<<<dim3((HH * HH + 1023) / 1024, 4), 256>>>(wq, wk, wv, wo);
    rmsnorm_kernel<<<NROWS, 256>>>(x, norm_w);

    // QKV projections: C = h @ W^T via mma.sync bf16 3-term split
    hmma_gemm<<<dim3(HH / GBN, NROWS / GBM, 3), 256, GEMM_SMEM>>>(
        phh, phl, pwh, pwl, pq, pk, pv);

    rope_apply_kernel<<<(NROWS * NH * 64 + 255) / 256, 256>>>(pos);

    flash_kernel<<<dim3(SS / 64, BB * NH), 256, fs>>>();

    // output projection: out = ctx @ wo^T (weight slot 3)
    hmma_gemm<<<dim3(HH / GBN, NROWS / GBM, 1), 256, GEMM_SMEM>>>(
        pch, pcl, pwh + (size_t)3 * HH * HH, pwl + (size_t)3 * HH * HH, out, out, out);
}

// round 6
// speedup vs baseline: 2.5072x; 1.6093x over previous
#include <cuda_runtime.h>
#include <cuda_bf16.h>
#include <math.h>
#include <stdint.h>

// Problem constants
#define BB   2
#define SS   2048
#define HH   2048
#define NH   16
#define DD   128
#define NROWS (BB*SS)          // 4096
#define KDIM  HH               // 2048
#define SCALE 0.08838834764831845f  // 1/sqrt(128)

__device__ __forceinline__ uint32_t smem_u32(const void* p) {
    uint32_t a;
    asm("{ .reg .u64 t; cvta.to.shared.u64 t, %1; cvt.u32.u64 %0, t; }" : "=r"(a) : "l"(p));
    return a;
}

#define LDSM4(R0, R1, R2, R3, ADDR) \
    asm volatile("ldmatrix.sync.aligned.m8n8.x4.shared.b16 {%0,%1,%2,%3}, [%4];" \
        : "=r"(R0), "=r"(R1), "=r"(R2), "=r"(R3) : "r"(ADDR))

#define LDSM4T(R0, R1, R2, R3, ADDR) \
    asm volatile("ldmatrix.sync.aligned.m8n8.x4.trans.shared.b16 {%0,%1,%2,%3}, [%4];" \
        : "=r"(R0), "=r"(R1), "=r"(R2), "=r"(R3) : "r"(ADDR))

#define MMA16816(D, A, B0, B1) \
    asm volatile("mma.sync.aligned.m16n8k16.row.col.f32.bf16.bf16.f32 " \
        "{%0,%1,%2,%3}, {%4,%5,%6,%7}, {%8,%9}, {%0,%1,%2,%3};" \
        : "+f"((D)[0]), "+f"((D)[1]), "+f"((D)[2]), "+f"((D)[3]) \
        : "r"((A)[0]), "r"((A)[1]), "r"((A)[2]), "r"((A)[3]), "r"(B0), "r"(B1))

#define CP_ASYNC16(DST, SRC) \
    asm volatile("cp.async.cg.shared.global [%0], [%1], 16;" :: "r"(DST), "l"(SRC))
#define CP_COMMIT() asm volatile("cp.async.commit_group;" ::: "memory")
#define CP_WAIT1()  asm volatile("cp.async.wait_group 1;" ::: "memory")
#define CP_WAIT0()  asm volatile("cp.async.wait_group 0;" ::: "memory")

// ============================ scratch globals =================================
__device__ __nv_bfloat16 g_h_hi[NROWS * HH];
__device__ __nv_bfloat16 g_h_lo[NROWS * HH];
__device__ __nv_bfloat16 g_w_hi[4 * HH * HH];
__device__ __nv_bfloat16 g_w_lo[4 * HH * HH];
__device__ __nv_bfloat16 g_ctx_hi[NROWS * HH];
__device__ __nv_bfloat16 g_ctx_lo[NROWS * HH];
__device__ float g_q[NROWS * HH];
__device__ float g_k[NROWS * HH];
__device__ float g_v[NROWS * HH];
// head-major bf16 hi/lo for attention: [(b*NH+h)*SS + s]*DD + d
__device__ __nv_bfloat16 g_qh[NROWS * HH];
__device__ __nv_bfloat16 g_ql[NROWS * HH];
__device__ __nv_bfloat16 g_kh[NROWS * HH];
__device__ __nv_bfloat16 g_kl[NROWS * HH];
__device__ __nv_bfloat16 g_vh[NROWS * HH];
__device__ __nv_bfloat16 g_vl[NROWS * HH];
__device__ float g_cos[SS * 64];
__device__ float g_sin[SS * 64];

// ============================ RoPE tables =====================================
__global__ void rope_table_kernel() {
    int idx = blockIdx.x * blockDim.x + threadIdx.x;
    if (idx >= SS * 64) return;
    int s = idx >> 6;
    int j = idx & 63;
    double inv = exp(-log(10000.0) * (double)(2 * j) / 128.0);
    double a = (double)s * inv;
    g_cos[idx] = (float)cos(a);
    g_sin[idx] = (float)sin(a);
}

// ============================ weight split ====================================
__global__ void __launch_bounds__(256) convert_w_kernel(const float* __restrict__ wq,
                                                        const float* __restrict__ wk,
                                                        const float* __restrict__ wv,
                                                        const float* __restrict__ wo) {
    int z = blockIdx.y;
    const float* src = (z == 0) ? wq : (z == 1) ? wk : (z == 2) ? wv : wo;
    size_t i = (size_t)blockIdx.x * 1024 + threadIdx.x * 4;
    if (i >= (size_t)HH * HH) return;
    float4 v = *(const float4*)(src + i);
    size_t o = (size_t)z * HH * HH + i;
    float vv[4] = {v.x, v.y, v.z, v.w};
#pragma unroll
    for (int t = 0; t < 4; t++) {
        __nv_bfloat16 hi = __float2bfloat16(vv[t]);
        g_w_hi[o + t] = hi;
        g_w_lo[o + t] = __float2bfloat16(vv[t] - __bfloat162float(hi));
    }
}

// ============================ RMSNorm → bf16 hi/lo ============================
__global__ void __launch_bounds__(256) rmsnorm_kernel(const float* __restrict__ x,
                                                      const float* __restrict__ w) {
    int row = blockIdx.x;
    const float* xr = x + (size_t)row * HH;
    int tid = threadIdx.x;

    float ss = 0.f;
#pragma unroll
    for (int t = 0; t < 8; t++) {
        float v = xr[tid + t * 256];
        ss += v * v;
    }
#pragma unroll
    for (int off = 16; off >= 1; off >>= 1)
        ss += __shfl_xor_sync(0xffffffffu, ss, off);
    __shared__ float red[8];
    if ((tid & 31) == 0) red[tid >> 5] = ss;
    __syncthreads();
    float tot = red[0] + red[1] + red[2] + red[3] + red[4] + red[5] + red[6] + red[7];
    float invn = rsqrtf(tot * (1.0f / (float)HH) + 1e-6f);
    size_t base = (size_t)row * HH;
#pragma unroll
    for (int t = 0; t < 8; t++) {
        int c = tid + t * 256;
        float v = w[c] * (xr[c] * invn);
        __nv_bfloat16 hi = __float2bfloat16(v);
        g_h_hi[base + c] = hi;
        g_h_lo[base + c] = __float2bfloat16(v - __bfloat162float(hi));
    }
}

// ============ HMMA GEMM: C[M,N] = A[M,K] * W[N,K]^T (3-term bf16 split) =======
#define GBM 128
#define GBN 128
#define GBK 32
#define LDA_B 80
#define ARR_BYTES (128 * LDA_B)
#define S_AH 0
#define S_AL (1 * ARR_BYTES)
#define S_BH (2 * ARR_BYTES)
#define S_BL (3 * ARR_BYTES)
#define STAGE (4 * ARR_BYTES)
#define GEMM_SMEM (2 * STAGE)
#define NC (KDIM / GBK)

__global__ void __launch_bounds__(256, 1)
hmma_gemm(const __nv_bfloat16* __restrict__ Ahp, const __nv_bfloat16* __restrict__ Alp,
          const __nv_bfloat16* __restrict__ Whp, const __nv_bfloat16* __restrict__ Wlp,
          float* __restrict__ C0, float* __restrict__ C1, float* __restrict__ C2) {
    extern __shared__ char smem[];
    uint32_t sb = smem_u32(smem);
    int tid = threadIdx.x;
    int wid = tid >> 5, lane = tid & 31;
    int bm = blockIdx.y * GBM;
    int bn = blockIdx.x * GBN;
    int z = blockIdx.z;
    const __nv_bfloat16* wh = Whp + (size_t)z * HH * HH;
    const __nv_bfloat16* wl = Wlp + (size_t)z * HH * HH;
    float* C = (z == 0) ? C0 : ((z == 1) ? C1 : C2);

    const uint4* gAh = (const uint4*)Ahp + (size_t)bm * 256;
    const uint4* gAl = (const uint4*)Alp + (size_t)bm * 256;
    const uint4* gBh = (const uint4*)wh + (size_t)bn * 256;
    const uint4* gBl = (const uint4*)wl + (size_t)bn * 256;

    int r0 = tid >> 2, c0 = tid & 3;
    int r1 = (tid + 256) >> 2, c1 = tid & 3;

#define ISSUE(chunk, buf) do { \
    uint32_t st_ = sb + (buf) * STAGE; \
    size_t g0_ = (size_t)r0 * 256 + (chunk) * 4 + c0; \
    size_t g1_ = (size_t)r1 * 256 + (chunk) * 4 + c1; \
    uint32_t s0_ = r0 * LDA_B + c0 * 16; \
    uint32_t s1_ = r1 * LDA_B + c1 * 16; \
    CP_ASYNC16(st_ + S_AH + s0_, gAh + g0_); \
    CP_ASYNC16(st_ + S_AH + s1_, gAh + g1_); \
    CP_ASYNC16(st_ + S_AL + s0_, gAl + g0_); \
    CP_ASYNC16(st_ + S_AL + s1_, gAl + g1_); \
    CP_ASYNC16(st_ + S_BH + s0_, gBh + g0_); \
    CP_ASYNC16(st_ + S_BH + s1_, gBh + g1_); \
    CP_ASYNC16(st_ + S_BL + s0_, gBl + g0_); \
    CP_ASYNC16(st_ + S_BL + s1_, gBl + g1_); \
} while (0)

    int wm = wid >> 2;
    int wn = wid & 3;

    uint32_t a_base = (uint32_t)(wm * 64 + (lane & 15)) * LDA_B + (lane >> 4) * 16;
    int q = lane >> 3;
    uint32_t b_base = (uint32_t)(wn * 32 + ((q >> 1) * 8) + (lane & 7)) * LDA_B + (q & 1) * 16;

    float acc[4][4][4];
#pragma unroll
    for (int mi = 0; mi < 4; mi++)
#pragma unroll
        for (int ni = 0; ni < 4; ni++)
#pragma unroll
            for (int e = 0; e < 4; e++) acc[mi][ni][e] = 0.f;

    ISSUE(0, 0);
    CP_COMMIT();

    for (int c = 0; c < NC; c++) {
        int buf = c & 1;
        if (c + 1 < NC) {
            ISSUE(c + 1, (c + 1) & 1);
            CP_COMMIT();
            CP_WAIT1();
        } else {
            CP_WAIT0();
        }
        __syncthreads();

        uint32_t st = sb + buf * STAGE;
#pragma unroll
        for (int ks = 0; ks < 2; ks++) {
            uint32_t a_hi[4][4], a_lo[4][4], b_hi[2][4], b_lo[2][4];
#pragma unroll
            for (int mi = 0; mi < 4; mi++) {
                uint32_t ao = a_base + mi * (16 * LDA_B) + ks * 32;
                LDSM4(a_hi[mi][0], a_hi[mi][1], a_hi[mi][2], a_hi[mi][3], st + S_AH + ao);
                LDSM4(a_lo[mi][0], a_lo[mi][1], a_lo[mi][2], a_lo[mi][3], st + S_AL + ao);
            }
#pragma unroll
            for (int nj = 0; nj < 2; nj++) {
                uint32_t bo = b_base + nj * (16 * LDA_B) + ks * 32;
                LDSM4(b_hi[nj][0], b_hi[nj][1], b_hi[nj][2], b_hi[nj][3], st + S_BH + bo);
                LDSM4(b_lo[nj][0], b_lo[nj][1], b_lo[nj][2], b_lo[nj][3], st + S_BL + bo);
            }
#pragma unroll
            for (int mi = 0; mi < 4; mi++)
#pragma unroll
                for (int ni = 0; ni < 4; ni++) {
                    int nj = ni >> 1, sel = (ni & 1) * 2;
                    MMA16816(acc[mi][ni], a_hi[mi], b_hi[nj][sel], b_hi[nj][sel + 1]);
                    MMA16816(acc[mi][ni], a_hi[mi], b_lo[nj][sel], b_lo[nj][sel + 1]);
                    MMA16816(acc[mi][ni], a_lo[mi], b_hi[nj][sel], b_hi[nj][sel + 1]);
                }
        }
        __syncthreads();
    }

    int row_in = (lane >> 2);
    int col_in = (lane & 3) * 2;
#pragma unroll
    for (int mi = 0; mi < 4; mi++) {
        int grow = bm + wm * 64 + mi * 16 + row_in;
#pragma unroll
        for (int ni = 0; ni < 4; ni++) {
            int gcol = bn + wn * 32 + ni * 8 + col_in;
            float* cr = C + (size_t)grow * HH + gcol;
            cr[0] = acc[mi][ni][0];
            cr[1] = acc[mi][ni][1];
            float* cr2 = cr + 8 * HH;
            cr2[0] = acc[mi][ni][2];
            cr2[1] = acc[mi][ni][3];
        }
    }
}

// ================= RoPE apply + bf16 hi/lo head-major Q/K/V ===================
__global__ void rope_apply_kernel(const int* __restrict__ pos_ids) {
    int idx = blockIdx.x * blockDim.x + threadIdx.x;
    if (idx >= NROWS * NH * 64) return;
    int j = idx & 63;
    int head = (idx >> 6) & 15;
    int n = idx >> 10;                  // b*SS + s
    int pos = pos_ids[n];
    float c = g_cos[pos * 64 + j];
    float s = g_sin[pos * 64 + j];
    size_t off = (size_t)n * HH + head * DD;
    int b = n >> 11, srow = n & 2047;
    size_t dst = ((size_t)(b * NH + head) * SS + srow) * DD;

    float q1 = g_q[off + j], q2 = g_q[off + j + 64];
    float qa = q1 * c - q2 * s;
    float qb = q2 * c + q1 * s;
    __nv_bfloat16 h;
    h = __float2bfloat16(qa); g_qh[dst + j] = h;      g_ql[dst + j] = __float2bfloat16(qa - __bfloat162float(h));
    h = __float2bfloat16(qb); g_qh[dst + j + 64] = h; g_ql[dst + j + 64] = __float2bfloat16(qb - __bfloat162float(h));

    float k1 = g_k[off + j], k2 = g_k[off + j + 64];
    float ka = k1 * c - k2 * s;
    float kb = k2 * c + k1 * s;
    h = __float2bfloat16(ka); g_kh[dst + j] = h;      g_kl[dst + j] = __float2bfloat16(ka - __bfloat162float(h));
    h = __float2bfloat16(kb); g_kh[dst + j + 64] = h; g_kl[dst + j + 64] = __float2bfloat16(kb - __bfloat162float(h));

    float v1 = g_v[off + j], v2 = g_v[off + j + 64];
    h = __float2bfloat16(v1); g_vh[dst + j] = h;      g_vl[dst + j] = __float2bfloat16(v1 - __bfloat162float(h));
    h = __float2bfloat16(v2); g_vh[dst + j + 64] = h; g_vl[dst + j + 64] = __float2bfloat16(v2 - __bfloat162float(h));
}

// ================== flash attention via mma.sync (bf16 split) =================
// CTA = (qtile of 128, b*NH). 256 threads / 8 warps; warp owns 16 query rows.
#define FBM 128
#define FBK 64
#define LDKB 272                         // bytes per smem row (136 bf16)
#define SQ_H 0
#define SQ_L (FBM * LDKB)                // 34816
#define F_ST0 (2 * FBM * LDKB)           // 69632
#define FST_KH 0
#define FST_KL (FBK * LDKB)
#define FST_VH (2 * FBK * LDKB)
#define FST_VL (3 * FBK * LDKB)
#define FSTAGE (4 * FBK * LDKB)          // 69632
#define FLASH_SMEM (F_ST0 + 2 * FSTAGE)  // 208896

__device__ __forceinline__ uint32_t pack_bf16(float lo_v, float hi_v) {
    __nv_bfloat162 p = __floats2bfloat162_rn(lo_v, hi_v);  // .x = lo half
    return *reinterpret_cast<uint32_t*>(&p);
}

__global__ void __launch_bounds__(256, 1) flash_mma() {
    extern __shared__ char smem[];
    uint32_t sb = smem_u32(smem);
    int tid = threadIdx.x, wid = tid >> 5, lane = tid & 31;
    int qt = 15 - blockIdx.x;          // heavy tiles first
    int bh = blockIdx.y;

    size_t qoff = ((size_t)bh * SS + (size_t)qt * FBM) * DD;
    const uint4* gQh = (const uint4*)(g_qh + qoff);
    const uint4* gQl = (const uint4*)(g_ql + qoff);
    const uint4* gKh = (const uint4*)(g_kh + (size_t)bh * SS * DD);
    const uint4* gKl = (const uint4*)(g_kl + (size_t)bh * SS * DD);
    const uint4* gVh = (const uint4*)(g_vh + (size_t)bh * SS * DD);
    const uint4* gVl = (const uint4*)(g_vl + (size_t)bh * SS * DD);

    // Q tile: 2048 uint4 per array
#pragma unroll
    for (int i = 0; i < 8; i++) {
        int u = tid + 256 * i;
        int r = u >> 4, cc = u & 15;
        uint32_t so = r * LDKB + cc * 16;
        CP_ASYNC16(sb + SQ_H + so, gQh + r * 16 + cc);
        CP_ASYNC16(sb + SQ_L + so, gQl + r * 16 + cc);
    }
    CP_COMMIT();

#define FISSUE(kt_, buf_) do { \
    uint32_t st_ = sb + F_ST0 + (buf_) * FSTAGE; \
    int kb_ = (kt_) * FBK; \
    _Pragma("unroll") \
    for (int i = 0; i < 4; i++) { \
        int u = tid + 256 * i; \
        int r = u >> 4, cc = u & 15; \
        uint32_t so = r * LDKB + cc * 16; \
        size_t g = (size_t)(kb_ + r) * 16 + cc; \
        CP_ASYNC16(st_ + FST_KH + so, gKh + g); \
        CP_ASYNC16(st_ + FST_KL + so, gKl + g); \
        CP_ASYNC16(st_ + FST_VH + so, gVh + g); \
        CP_ASYNC16(st_ + FST_VL + so, gVl + g); \
    } \
} while (0)

    int ntiles = 2 * qt + 2;
    FISSUE(0, 0);
    CP_COMMIT();

    uint32_t qfh[8][4], qfl[8][4];
    float oacc[16][4];
#pragma unroll
    for (int nd = 0; nd < 16; nd++)
#pragma unroll
        for (int e = 0; e < 4; e++) oacc[nd][e] = 0.f;
    float m_cur[2] = {-1e30f, -1e30f}, l_cur[2] = {0.f, 0.f};

    // ldmatrix lane address components
    int lrow = (lane & 7) + ((lane >> 3) & 1) * 8;   // A-style row (mats 0/1 stacked)
    int lsel = (lane >> 4) * 8;                       // second 8-col half for mats 2/3
    int krow = (lane & 7) + (lane >> 4) * 8;          // K: mats 2/3 = +8 rows
    int ksel = ((lane >> 3) & 1) * 8;                 // K: mats 1/3 = +8 cols

    for (int kt = 0; kt < ntiles; kt++) {
        if (kt + 1 < ntiles) {
            FISSUE(kt + 1, (kt + 1) & 1);
            CP_COMMIT();
            CP_WAIT1();
        } else {
            CP_WAIT0();
        }
        __syncthreads();

        if (kt == 0) {
#pragma unroll
            for (int j = 0; j < 8; j++) {
                uint32_t ao = (uint32_t)(wid * 16 + lrow) * LDKB + (j * 16 + lsel) * 2;
                LDSM4(qfh[j][0], qfh[j][1], qfh[j][2], qfh[j][3], sb + SQ_H + ao);
                LDSM4(qfl[j][0], qfl[j][1], qfl[j][2], qfl[j][3], sb + SQ_L + ao);
            }
        }

        uint32_t st = sb + F_ST0 + (kt & 1) * FSTAGE;

        // ---- S = Q K^T (3-term split), 128x64 tile, warp rows wid*16..+15 ----
        float sacc[8][4];
#pragma unroll
        for (int n = 0; n < 8; n++)
#pragma unroll
            for (int e = 0; e < 4; e++) sacc[n][e] = 0.f;

#pragma unroll
        for (int j = 0; j < 8; j++) {
#pragma unroll
            for (int p = 0; p < 4; p++) {
                uint32_t ka = st + FST_KH + (uint32_t)(p * 16 + krow) * LDKB + (j * 16 + ksel) * 2;
                uint32_t bh0, bh1, bh2, bh3, bl0, bl1, bl2, bl3;
                LDSM4(bh0, bh1, bh2, bh3, ka);
                LDSM4(bl0, bl1, bl2, bl3, ka + (FST_KL - FST_KH));
                MMA16816(sacc[2 * p], qfh[j], bh0, bh1);
                MMA16816(sacc[2 * p], qfh[j], bl0, bl1);
                MMA16816(sacc[2 * p], qfl[j], bh0, bh1);
                MMA16816(sacc[2 * p + 1], qfh[j], bh2, bh3);
                MMA16816(sacc[2 * p + 1], qfh[j], bl2, bl3);
                MMA16816(sacc[2 * p + 1], qfl[j], bh2, bh3);
            }
        }

        // ---- scale + causal mask ----
        int row_g0 = qt * FBM + wid * 16 + (lane >> 2);
        bool diag = (kt >= 2 * qt);
#pragma unroll
        for (int n = 0; n < 8; n++)
#pragma unroll
            for (int e = 0; e < 4; e++) {
                float v = sacc[n][e] * SCALE;
                if (diag) {
                    int key = kt * FBK + n * 8 + (lane & 3) * 2 + (e & 1);
                    int row = row_g0 + ((e >= 2) ? 8 : 0);
                    if (key > row) v -= 10000.f;
                }
                sacc[n][e] = v;
            }

        // ---- online softmax (rows fully within warp; quad = 4 lanes) ----
#pragma unroll
        for (int rr = 0; rr < 2; rr++) {
            int e0 = rr * 2;
            float mx = -1e30f;
#pragma unroll
            for (int n = 0; n < 8; n++)
                mx = fmaxf(mx, fmaxf(sacc[n][e0], sacc[n][e0 + 1]));
            mx = fmaxf(mx, __shfl_xor_sync(0xffffffffu, mx, 1));
            mx = fmaxf(mx, __shfl_xor_sync(0xffffffffu, mx, 2));
            float mnew = fmaxf(m_cur[rr], mx);
            float alpha = __expf(m_cur[rr] - mnew);
            m_cur[rr] = mnew;
            float rs = 0.f;
#pragma unroll
            for (int n = 0; n < 8; n++) {
                sacc[n][e0] = __expf(sacc[n][e0] - mnew);
                sacc[n][e0 + 1] = __expf(sacc[n][e0 + 1] - mnew);
                rs += sacc[n][e0] + sacc[n][e0 + 1];
            }
            rs += __shfl_xor_sync(0xffffffffu, rs, 1);
            rs += __shfl_xor_sync(0xffffffffu, rs, 2);
            l_cur[rr] = l_cur[rr] * alpha + rs;
#pragma unroll
            for (int nd = 0; nd < 16; nd++) {
                oacc[nd][e0] *= alpha;
                oacc[nd][e0 + 1] *= alpha;
            }
        }

        // ---- O += P V (3-term split); P frags built from sacc registers ----
#pragma unroll
        for (int jk = 0; jk < 4; jk++) {
            uint32_t pah[4], pal[4];
#pragma unroll
            for (int half = 0; half < 2; half++) {   // half 0: ntile 2jk ; 1: 2jk+1
                int n = 2 * jk + half;
#pragma unroll
                for (int rr = 0; rr < 2; rr++) {
                    float p0 = sacc[n][rr * 2], p1 = sacc[n][rr * 2 + 1];
                    __nv_bfloat16 h0 = __float2bfloat16(p0);
                    __nv_bfloat16 h1 = __float2bfloat16(p1);
                    __nv_bfloat162 hp; hp.x = h0; hp.y = h1;
                    pah[half * 2 + rr] = *reinterpret_cast<uint32_t*>(&hp);
                    pal[half * 2 + rr] = pack_bf16(p0 - __bfloat162float(h0),
                                                   p1 - __bfloat162float(h1));
                }
            }
            // operand order: a0=(r,k0-7) a1=(r+8,k0-7) a2=(r,k8-15) a3=(r+8,k8-15)
            uint32_t pa_h[4] = {pah[0], pah[1], pah[2], pah[3]};
            uint32_t pa_l[4] = {pal[0], pal[1], pal[2], pal[3]};
#pragma unroll
            for (int q = 0; q < 8; q++) {
                uint32_t va = st + FST_VH + (uint32_t)(jk * 16 + lrow) * LDKB + (q * 16 + lsel) * 2;
                uint32_t vh0, vh1, vh2, vh3, vl0, vl1, vl2, vl3;
                LDSM4T(vh0, vh1, vh2, vh3, va);
                LDSM4T(vl0, vl1, vl2, vl3, va + (FST_VL - FST_VH));
                MMA16816(oacc[2 * q], pa_h, vh0, vh1);
                MMA16816(oacc[2 * q], pa_h, vl0, vl1);
                MMA16816(oacc[2 * q], pa_l, vh0, vh1);
                MMA16816(oacc[2 * q + 1], pa_h, vh2, vh3);
                MMA16816(oacc[2 * q + 1], pa_h, vl2, vl3);
                MMA16816(oacc[2 * q + 1], pa_l, vh2, vh3);
            }
        }
        __syncthreads();
    }

    // ---- epilogue: normalize, write ctx hi/lo (row-major [n][h*128+d]) ----
    int b = bh >> 4, h = bh & 15;
    float inv[2] = {1.f / l_cur[0], 1.f / l_cur[1]};
#pragma unroll
    for (int rr = 0; rr < 2; rr++) {
        int row = qt * FBM + wid * 16 + (lane >> 2) + rr * 8;
        size_t base = ((size_t)(b * SS + row)) * HH + h * DD + (lane & 3) * 2;
#pragma unroll
        for (int nd = 0; nd < 16; nd++) {
            float o0 = oacc[nd][rr * 2] * inv[rr];
            float o1 = oacc[nd][rr * 2 + 1] * inv[rr];
            __nv_bfloat16 h0 = __float2bfloat16(o0);
            __nv_bfloat16 h1 = __float2bfloat16(o1);
            size_t d = base + nd * 8;
            g_ctx_hi[d] = h0;
            g_ctx_hi[d + 1] = h1;
            g_ctx_lo[d] = __float2bfloat16(o0 - __bfloat162float(h0));
            g_ctx_lo[d + 1] = __float2bfloat16(o1 - __bfloat162float(h1));
        }
    }
}

// ============================ launch ==========================================
extern "C" void kernel_launch(void* const* d_in, const int* in_sizes, int n_in,
                              void* d_out, int out_size) {
    const float* x      = (const float*)d_in[0];
    const float* norm_w = (const float*)d_in[1];
    const float* wq     = (const float*)d_in[2];
    const float* wk     = (const float*)d_in[3];
    const float* wv     = (const float*)d_in[4];
    const float* wo     = (const float*)d_in[5];
    const int*   pos    = (const int*)d_in[6];
    float* out = (float*)d_out;

    __nv_bfloat16 *phh, *phl, *pwh, *pwl, *pch, *pcl;
    float *pq, *pk, *pv;
    cudaGetSymbolAddress((void**)&phh, g_h_hi);
    cudaGetSymbolAddress((void**)&phl, g_h_lo);
    cudaGetSymbolAddress((void**)&pwh, g_w_hi);
    cudaGetSymbolAddress((void**)&pwl, g_w_lo);
    cudaGetSymbolAddress((void**)&pch, g_ctx_hi);
    cudaGetSymbolAddress((void**)&pcl, g_ctx_lo);
    cudaGetSymbolAddress((void**)&pq, g_q);
    cudaGetSymbolAddress((void**)&pk, g_k);
    cudaGetSymbolAddress((void**)&pv, g_v);

    cudaFuncSetAttribute(hmma_gemm, cudaFuncAttributeMaxDynamicSharedMemorySize, GEMM_SMEM);
    cudaFuncSetAttribute(flash_mma, cudaFuncAttributeMaxDynamicSharedMemorySize, FLASH_SMEM);

    rope_table_kernel<<<(SS * 64 + 255) / 256, 256>>>();
    convert_w_kernel<<<dim3((HH * HH + 1023) / 1024, 4), 256>>>(wq, wk, wv, wo);
    rmsnorm_kernel<<<NROWS, 256>>>(x, norm_w);

    // QKV projections
    hmma_gemm<<<dim3(HH / GBN, NROWS / GBM, 3), 256, GEMM_SMEM>>>(
        phh, phl, pwh, pwl, pq, pk, pv);

    // RoPE + head-major bf16 split q/k/v
    rope_apply_kernel<<<(NROWS * NH * 64 + 255) / 256, 256>>>(pos);

    // attention on tensor cores
    flash_mma<<<dim3(SS / FBM, BB * NH), 256, FLASH_SMEM>>>();

    // output projection
    hmma_gemm<<<dim3(HH / GBN, NROWS / GBM, 1), 256, GEMM_SMEM>>>(
        pch, pcl, pwh + (size_t)3 * HH * HH, pwl + (size_t)3 * HH * HH, out, out, out);
}